// round 6
// baseline (speedup 1.0000x reference)
#include <cuda_runtime.h>
#include <cstdint>
#include <math.h>

// Problem constants (fixed by the dataset)
#define MAX_N 50000
#define MAX_E 400000
#define D_IN 128
#define HID 32
#define HEADS 8
#define H1DIM (HEADS * HID)   // 256
#define OUTD 16
#define NEG_SLOPE 0.2f

// ---------------- static scratch (no allocations allowed) ----------------
__device__ float g_xl1[(size_t)MAX_N * H1DIM];
__device__ float g_xr1[(size_t)MAX_N * H1DIM];
__device__ float g_h1 [(size_t)MAX_N * H1DIM];
__device__ float g_xl2[(size_t)MAX_N * HID];
__device__ float g_xr2[(size_t)MAX_N * HID];
__device__ int   g_counts[MAX_N];
__device__ int   g_cursor[MAX_N];
__device__ int   g_rowstart[MAX_N + 1];
__device__ int   g_col[MAX_E + MAX_N];

// ---------------- CSR build ----------------
__global__ void zero_counts_kernel(int n) {
    int t = blockIdx.x * blockDim.x + threadIdx.x;
    if (t < n) g_counts[t] = 0;
}

// edge_index is int32 (JAX x64 is disabled; the reference's int64 request downcasts)
__global__ void hist_kernel(const int* __restrict__ ei, int E, int N) {
    int t = blockIdx.x * blockDim.x + threadIdx.x;
    if (t < E) {
        int d = ei[E + t];
        if ((unsigned)d < (unsigned)N) atomicAdd(&g_counts[d], 1);
    }
}

// single-block scan of (counts[i] + 1)  (+1 = self loop) -> exclusive rowstart
__global__ void scan_kernel(int n) {
    __shared__ int warp_sums[32];
    __shared__ int carry_s;
    int tid = threadIdx.x;
    int lane = tid & 31, wid = tid >> 5;
    if (tid == 0) carry_s = 0;
    __syncthreads();
    for (int base = 0; base < n; base += 1024) {
        int i = base + tid;
        int v = (i < n) ? g_counts[i] + 1 : 0;
        int x = v;
        #pragma unroll
        for (int d = 1; d < 32; d <<= 1) {
            int t = __shfl_up_sync(0xFFFFFFFFu, x, d);
            if (lane >= d) x += t;
        }
        if (lane == 31) warp_sums[wid] = x;
        __syncthreads();
        if (tid < 32) {
            int w = warp_sums[tid];
            #pragma unroll
            for (int d = 1; d < 32; d <<= 1) {
                int t = __shfl_up_sync(0xFFFFFFFFu, w, d);
                if (tid >= d) w += t;
            }
            warp_sums[tid] = w;
        }
        __syncthreads();
        int blockIncl = x + (wid > 0 ? warp_sums[wid - 1] : 0);
        int carry = carry_s;
        int total = warp_sums[31];
        int excl = carry + blockIncl - v;
        if (i < n) { g_rowstart[i] = excl; g_cursor[i] = excl; }
        __syncthreads();
        if (tid == 0) carry_s += total;
        __syncthreads();
    }
    if (tid == 0) g_rowstart[n] = carry_s;
}

__global__ void scatter_kernel(const int* __restrict__ ei, int E, int N) {
    int t = blockIdx.x * blockDim.x + threadIdx.x;
    if (t < E) {
        int d = ei[E + t];
        int s = ei[t];
        if ((unsigned)d < (unsigned)N && (unsigned)s < (unsigned)N) {
            int slot = atomicAdd(&g_cursor[d], 1);
            g_col[slot] = s;
        }
    } else if (t < E + N) {
        int i = t - E;
        int slot = atomicAdd(&g_cursor[i], 1);
        g_col[slot] = i;
    }
}

// ---------------- register-blocked SGEMM ----------------
// C[M,N] = A[M,K] @ B[K,N].  A: external ptr if a_ext != nullptr, else g_h1.
// C selected by dest: 0: g_xl1, 1: g_xr1, 2: g_xl2, 3: g_xr2.
template <int BM, int BN, int BK, int TM, int TN>
__global__ void __launch_bounds__((BM / TM) * (BN / TN))
sgemm_kernel(const float* __restrict__ a_ext, const float* __restrict__ B,
             int M, int N, int K, int dest) {
    const float* A = a_ext ? a_ext : (const float*)g_h1;
    float* C = (dest == 0) ? g_xl1 : (dest == 1) ? g_xr1
             : (dest == 2) ? g_xl2 : g_xr2;

    constexpr int TCOLS = BN / TN;
    constexpr int TROWS = BM / TM;
    constexpr int NT = TCOLS * TROWS;
    __shared__ float As[BK][BM + 4];
    __shared__ float Bs[BK][BN];
    int tid = threadIdx.x;
    int tr = tid / TCOLS, tc = tid % TCOLS;
    int row0 = blockIdx.y * BM, col0 = blockIdx.x * BN;
    float acc[TM][TN];
    #pragma unroll
    for (int i = 0; i < TM; i++)
        #pragma unroll
        for (int j = 0; j < TN; j++) acc[i][j] = 0.f;

    for (int k0 = 0; k0 < K; k0 += BK) {
        #pragma unroll
        for (int idx = tid; idx < BM * BK / 4; idx += NT) {
            int r = idx / (BK / 4), c4 = idx % (BK / 4);
            float4 v = make_float4(0.f, 0.f, 0.f, 0.f);
            int gr = row0 + r;
            if (gr < M) v = *(const float4*)(A + (size_t)gr * K + k0 + c4 * 4);
            As[c4 * 4 + 0][r] = v.x;
            As[c4 * 4 + 1][r] = v.y;
            As[c4 * 4 + 2][r] = v.z;
            As[c4 * 4 + 3][r] = v.w;
        }
        #pragma unroll
        for (int idx = tid; idx < BK * BN / 4; idx += NT) {
            int r = idx / (BN / 4), c4 = idx % (BN / 4);
            *(float4*)&Bs[r][c4 * 4] = *(const float4*)(B + (size_t)(k0 + r) * N + col0 + c4 * 4);
        }
        __syncthreads();
        #pragma unroll
        for (int k = 0; k < BK; k++) {
            float ra[TM], rb[TN];
            #pragma unroll
            for (int i = 0; i < TM; i++) ra[i] = As[k][tr * TM + i];
            #pragma unroll
            for (int j = 0; j < TN; j++) rb[j] = Bs[k][tc * TN + j];
            #pragma unroll
            for (int i = 0; i < TM; i++)
                #pragma unroll
                for (int j = 0; j < TN; j++) acc[i][j] += ra[i] * rb[j];
        }
        __syncthreads();
    }
    #pragma unroll
    for (int i = 0; i < TM; i++) {
        int gr = row0 + tr * TM + i;
        if (gr < M) {
            if constexpr (TN % 4 == 0) {
                #pragma unroll
                for (int j = 0; j < TN; j += 4)
                    *(float4*)(C + (size_t)gr * N + col0 + tc * TN + j) =
                        make_float4(acc[i][j], acc[i][j + 1], acc[i][j + 2], acc[i][j + 3]);
            } else {
                #pragma unroll
                for (int j = 0; j < TN; j++)
                    C[(size_t)gr * N + col0 + tc * TN + j] = acc[i][j];
            }
        }
    }
}

// ---------------- GAT layer 1: warp per dst node, online softmax ----------------
__global__ void gat1_kernel(const float* __restrict__ att, const float* __restrict__ bias,
                            int n) {
    int warp = (blockIdx.x * blockDim.x + threadIdx.x) >> 5;
    int lane = threadIdx.x & 31;
    if (warp >= n) return;
    int head = lane >> 2, sub = lane & 3;

    const float4* xr4 = (const float4*)(g_xr1 + (size_t)warp * H1DIM + lane * 8);
    float4 r0 = xr4[0], r1 = xr4[1];
    float xrv[8] = {r0.x, r0.y, r0.z, r0.w, r1.x, r1.y, r1.z, r1.w};
    float av[8];
    #pragma unroll
    for (int k = 0; k < 8; k++) av[k] = att[head * HID + sub * 8 + k];

    float acc[8] = {0.f, 0.f, 0.f, 0.f, 0.f, 0.f, 0.f, 0.f};
    float m = -1e30f, denom = 0.f;

    int s = g_rowstart[warp], e = g_rowstart[warp + 1];
    for (int j = s; j < e; j++) {
        int src = g_col[j];
        const float4* p4 = (const float4*)(g_xl1 + (size_t)src * H1DIM + lane * 8);
        float4 a = p4[0], b = p4[1];
        float xv[8] = {a.x, a.y, a.z, a.w, b.x, b.y, b.z, b.w};
        float logit = 0.f;
        #pragma unroll
        for (int k = 0; k < 8; k++) {
            float t = xv[k] + xrv[k];
            t = t > 0.f ? t : NEG_SLOPE * t;
            logit += t * av[k];
        }
        logit += __shfl_xor_sync(0xFFFFFFFFu, logit, 1);
        logit += __shfl_xor_sync(0xFFFFFFFFu, logit, 2);
        float mn = fmaxf(m, logit);
        float sc = __expf(m - mn);
        float w  = __expf(logit - mn);
        denom = denom * sc + w;
        #pragma unroll
        for (int k = 0; k < 8; k++) acc[k] = acc[k] * sc + w * xv[k];
        m = mn;
    }
    float inv = 1.f / fmaxf(denom, 1e-16f);
    float o[8];
    #pragma unroll
    for (int k = 0; k < 8; k++) {
        float v = acc[k] * inv + bias[lane * 8 + k];
        o[k] = v > 0.f ? v : expm1f(v);      // ELU
    }
    float4* out4 = (float4*)(g_h1 + (size_t)warp * H1DIM + lane * 8);
    out4[0] = make_float4(o[0], o[1], o[2], o[3]);
    out4[1] = make_float4(o[4], o[5], o[6], o[7]);
}

// ---------------- GAT layer 2 (1 head) + fused final linear ----------------
__global__ void gat2_kernel(const float* __restrict__ att, const float* __restrict__ bias,
                            const float* __restrict__ Wlin, const float* __restrict__ blin,
                            float* __restrict__ out, int n) {
    __shared__ float sh[8][HID];
    int warp = (blockIdx.x * blockDim.x + threadIdx.x) >> 5;
    int lane = threadIdx.x & 31;
    int wl = threadIdx.x >> 5;
    if (warp >= n) return;

    float xrv = g_xr2[(size_t)warp * HID + lane];
    float av  = att[lane];
    float acc = 0.f, m = -1e30f, denom = 0.f;

    int s = g_rowstart[warp], e = g_rowstart[warp + 1];
    for (int j = s; j < e; j++) {
        int src = g_col[j];
        float xv = g_xl2[(size_t)src * HID + lane];
        float t = xv + xrv;
        t = t > 0.f ? t : NEG_SLOPE * t;
        float logit = t * av;
        #pragma unroll
        for (int d = 16; d >= 1; d >>= 1) logit += __shfl_xor_sync(0xFFFFFFFFu, logit, d);
        float mn = fmaxf(m, logit);
        float sc = __expf(m - mn);
        float w  = __expf(logit - mn);
        denom = denom * sc + w;
        acc = acc * sc + w * xv;
        m = mn;
    }
    float h2 = acc / fmaxf(denom, 1e-16f) + bias[lane];
    h2 = h2 > 0.f ? h2 : expm1f(h2);          // ELU

    sh[wl][lane] = h2;
    __syncwarp();
    if (lane < OUTD) {
        float sum = blin[lane];
        #pragma unroll
        for (int c = 0; c < HID; c++) sum += sh[wl][c] * Wlin[c * OUTD + lane];
        out[(size_t)warp * OUTD + lane] = sum;
    }
}

// ---------------- launch (kernel launches ONLY — fully capturable) ----------------
extern "C" void kernel_launch(void* const* d_in, const int* in_sizes, int n_in,
                              void* d_out, int out_size) {
    const float* x    = (const float*)d_in[0];
    const int*   ei   = (const int*)d_in[1];     // int32! (JAX x64 disabled)
    const float* W1l  = (const float*)d_in[2];
    const float* W1r  = (const float*)d_in[3];
    const float* att1 = (const float*)d_in[4];
    const float* b1   = (const float*)d_in[5];
    const float* W2l  = (const float*)d_in[6];
    const float* W2r  = (const float*)d_in[7];
    const float* att2 = (const float*)d_in[8];
    const float* b2   = (const float*)d_in[9];
    const float* Wlin = (const float*)d_in[10];
    const float* blin = (const float*)d_in[11];
    float* out = (float*)d_out;

    int N = in_sizes[0] / D_IN;
    int E = in_sizes[1] / 2;

    // --- CSR build (by destination) ---
    zero_counts_kernel<<<(N + 255) / 256, 256>>>(N);
    hist_kernel<<<(E + 255) / 256, 256>>>(ei, E, N);
    scan_kernel<<<1, 1024>>>(N);
    scatter_kernel<<<(E + N + 255) / 256, 256>>>(ei, E, N);

    // --- layer-1 transforms: xl1 = x@W1l, xr1 = x@W1r ---
    {
        dim3 grid(H1DIM / 128, (N + 127) / 128);
        sgemm_kernel<128, 128, 16, 8, 8><<<grid, 256>>>(x, W1l, N, H1DIM, D_IN, 0);
        sgemm_kernel<128, 128, 16, 8, 8><<<grid, 256>>>(x, W1r, N, H1DIM, D_IN, 1);
    }

    // --- GAT layer 1 (warp per node) ---
    gat1_kernel<<<(N * 32 + 255) / 256, 256>>>(att1, b1, N);

    // --- layer-2 transforms: xl2 = h1@W2l, xr2 = h1@W2r ---
    {
        dim3 grid(HID / 32, (N + 127) / 128);
        sgemm_kernel<128, 32, 32, 8, 2><<<grid, 256>>>(nullptr, W2l, N, HID, H1DIM, 2);
        sgemm_kernel<128, 32, 32, 8, 2><<<grid, 256>>>(nullptr, W2r, N, HID, H1DIM, 3);
    }

    // --- GAT layer 2 + final linear ---
    gat2_kernel<<<(N * 32 + 255) / 256, 256>>>(att2, b2, Wlin, blin, out, N);
}

// round 8
// speedup vs baseline: 1.2586x; 1.2586x over previous
#include <cuda_runtime.h>
#include <cuda_bf16.h>
#include <cstdint>
#include <math.h>

// Problem constants (fixed by the dataset)
#define MAX_N 50000
#define MAX_E 400000
#define D_IN 128
#define HID 32
#define HEADS 8
#define H1DIM (HEADS * HID)   // 256
#define OUTD 16
#define NEG_SLOPE 0.2f

// ---------------- static scratch (no allocations allowed) ----------------
__device__ float g_xl1[(size_t)MAX_N * H1DIM];
__device__ float g_xr1[(size_t)MAX_N * H1DIM];
__device__ float g_xl2[(size_t)MAX_N * HID];
__device__ float g_xr2[(size_t)MAX_N * HID];
// split-bf16 operands (stored as raw u16)
__device__ __align__(16) uint16_t g_xh [(size_t)MAX_N * D_IN];
__device__ __align__(16) uint16_t g_xlo[(size_t)MAX_N * D_IN];
__device__ __align__(16) uint16_t g_h1h[(size_t)MAX_N * H1DIM];
__device__ __align__(16) uint16_t g_h1l[(size_t)MAX_N * H1DIM];
// weights: split + transposed to [N][K]
__device__ __align__(16) uint16_t g_w1lh[H1DIM * D_IN], g_w1ll[H1DIM * D_IN];
__device__ __align__(16) uint16_t g_w1rh[H1DIM * D_IN], g_w1rl[H1DIM * D_IN];
__device__ __align__(16) uint16_t g_w2lh[HID * H1DIM], g_w2ll[HID * H1DIM];
__device__ __align__(16) uint16_t g_w2rh[HID * H1DIM], g_w2rl[HID * H1DIM];
// CSR
__device__ int g_counts[MAX_N];
__device__ int g_cursor[MAX_N];
__device__ int g_rowstart[MAX_N + 1];
__device__ int g_col[MAX_E + MAX_N];

// ---------------- helpers ----------------
__device__ __forceinline__ void split_bf16(float f, uint16_t& hi, uint16_t& lo) {
    __nv_bfloat16 h = __float2bfloat16_rn(f);
    __nv_bfloat16 l = __float2bfloat16_rn(f - __bfloat162float(h));
    hi = __bfloat16_as_ushort(h);
    lo = __bfloat16_as_ushort(l);
}

__device__ __forceinline__ void mma16816(float* c, const uint32_t* a, uint32_t b0, uint32_t b1) {
    asm volatile(
        "mma.sync.aligned.m16n8k16.row.col.f32.bf16.bf16.f32 "
        "{%0,%1,%2,%3}, {%4,%5,%6,%7}, {%8,%9}, {%0,%1,%2,%3};"
        : "+f"(c[0]), "+f"(c[1]), "+f"(c[2]), "+f"(c[3])
        : "r"(a[0]), "r"(a[1]), "r"(a[2]), "r"(a[3]), "r"(b0), "r"(b1));
}

// ---------------- CSR build ----------------
__global__ void zero_counts_kernel(int n) {
    int t = blockIdx.x * blockDim.x + threadIdx.x;
    if (t < n) g_counts[t] = 0;
}

// edge_index is int32 (JAX x64 disabled downcasts the reference's int64)
__global__ void hist_kernel(const int* __restrict__ ei, int E, int N) {
    int t = blockIdx.x * blockDim.x + threadIdx.x;
    if (t < E) {
        int d = ei[E + t];
        if ((unsigned)d < (unsigned)N) atomicAdd(&g_counts[d], 1);
    }
}

__global__ void scan_kernel(int n) {
    __shared__ int warp_sums[32];
    __shared__ int carry_s;
    int tid = threadIdx.x;
    int lane = tid & 31, wid = tid >> 5;
    if (tid == 0) carry_s = 0;
    __syncthreads();
    for (int base = 0; base < n; base += 1024) {
        int i = base + tid;
        int v = (i < n) ? g_counts[i] + 1 : 0;
        int x = v;
        #pragma unroll
        for (int d = 1; d < 32; d <<= 1) {
            int t = __shfl_up_sync(0xFFFFFFFFu, x, d);
            if (lane >= d) x += t;
        }
        if (lane == 31) warp_sums[wid] = x;
        __syncthreads();
        if (tid < 32) {
            int w = warp_sums[tid];
            #pragma unroll
            for (int d = 1; d < 32; d <<= 1) {
                int t = __shfl_up_sync(0xFFFFFFFFu, w, d);
                if (tid >= d) w += t;
            }
            warp_sums[tid] = w;
        }
        __syncthreads();
        int blockIncl = x + (wid > 0 ? warp_sums[wid - 1] : 0);
        int carry = carry_s;
        int total = warp_sums[31];
        int excl = carry + blockIncl - v;
        if (i < n) { g_rowstart[i] = excl; g_cursor[i] = excl; }
        __syncthreads();
        if (tid == 0) carry_s += total;
        __syncthreads();
    }
    if (tid == 0) g_rowstart[n] = carry_s;
}

__global__ void scatter_kernel(const int* __restrict__ ei, int E, int N) {
    int t = blockIdx.x * blockDim.x + threadIdx.x;
    if (t < E) {
        int d = ei[E + t];
        int s = ei[t];
        if ((unsigned)d < (unsigned)N && (unsigned)s < (unsigned)N) {
            int slot = atomicAdd(&g_cursor[d], 1);
            g_col[slot] = s;
        }
    } else if (t < E + N) {
        int i = t - E;
        int slot = atomicAdd(&g_cursor[i], 1);
        g_col[slot] = i;
    }
}

// ---------------- conversions ----------------
__global__ void split_x_kernel(const float* __restrict__ x, int total) {
    int t = blockIdx.x * blockDim.x + threadIdx.x;
    if (t < total) {
        uint16_t hi, lo;
        split_bf16(x[t], hi, lo);
        g_xh[t] = hi;
        g_xlo[t] = lo;
    }
}

// split + transpose weights: W[K][N] f32 -> Wt_hi/Wt_lo [N][K] bf16
// blockIdx.y selects matrix.
__global__ void split_w_kernel(const float* __restrict__ W1l, const float* __restrict__ W1r,
                               const float* __restrict__ W2l, const float* __restrict__ W2r) {
    int m = blockIdx.y;
    const float* src; uint16_t *dh, *dl; int K, N;
    if (m == 0)      { src = W1l; dh = g_w1lh; dl = g_w1ll; K = D_IN;  N = H1DIM; }
    else if (m == 1) { src = W1r; dh = g_w1rh; dl = g_w1rl; K = D_IN;  N = H1DIM; }
    else if (m == 2) { src = W2l; dh = g_w2lh; dl = g_w2ll; K = H1DIM; N = HID; }
    else             { src = W2r; dh = g_w2rh; dl = g_w2rl; K = H1DIM; N = HID; }
    int total = K * N;
    for (int t = blockIdx.x * blockDim.x + threadIdx.x; t < total; t += gridDim.x * blockDim.x) {
        int k = t / N, n = t % N;
        uint16_t hi, lo;
        split_bf16(src[t], hi, lo);
        dh[n * K + k] = hi;
        dl[n * K + k] = lo;
    }
}

// ---------------- bf16x3 tensor-core GEMM ----------------
// C[M,N] = A[M,K] @ W[K,N] in ~fp32 precision via Ah*Bh + Ah*Bl + Al*Bh.
// A split arrays selected by asel (0: x, 1: h1); B by bsel (0..3); C by dest (0..3).
template <int BM, int BN, int BK, int WM, int WN>
__global__ void __launch_bounds__((BM / WM) * (BN / WN) * 32, 1)
mma_gemm_kernel(int M, int N, int K, int asel, int bsel, int dest) {
    const uint16_t* Ah = asel == 0 ? g_xh  : g_h1h;
    const uint16_t* Al = asel == 0 ? g_xlo : g_h1l;
    const uint16_t *Bh, *Bl;
    if (bsel == 0)      { Bh = g_w1lh; Bl = g_w1ll; }
    else if (bsel == 1) { Bh = g_w1rh; Bl = g_w1rl; }
    else if (bsel == 2) { Bh = g_w2lh; Bl = g_w2ll; }
    else                { Bh = g_w2rh; Bl = g_w2rl; }
    float* C = (dest == 0) ? g_xl1 : (dest == 1) ? g_xr1
             : (dest == 2) ? g_xl2 : g_xr2;

    constexpr int WARPS_M = BM / WM;
    constexpr int WARPS_N = BN / WN;
    constexpr int THREADS = WARPS_M * WARPS_N * 32;
    constexpr int MT = WM / 16;
    constexpr int NT = WN / 8;
    constexpr int AST = BK + 8;             // halves; stride 40 -> conflict-free frags

    __shared__ uint16_t sA[2 * BM * AST];   // [hi | lo]
    __shared__ uint16_t sB[2 * BN * AST];
    constexpr int ALO = BM * AST;
    constexpr int BLO = BN * AST;

    int tid = threadIdx.x;
    int wid = tid >> 5, lane = tid & 31;
    int gid = lane >> 2, tig = lane & 3;
    int wm = wid / WARPS_N, wn = wid % WARPS_N;
    int row0 = blockIdx.y * BM;
    int n0 = blockIdx.x * BN;

    float acc[MT][NT][4];
    #pragma unroll
    for (int i = 0; i < MT; i++)
        #pragma unroll
        for (int j = 0; j < NT; j++)
            #pragma unroll
            for (int q = 0; q < 4; q++) acc[i][j][q] = 0.f;

    const uint4 z4 = make_uint4(0, 0, 0, 0);
    for (int k0 = 0; k0 < K; k0 += BK) {
        // load A tile (hi+lo), zero-filled past M
        #pragma unroll
        for (int idx = tid; idx < BM * (BK / 8); idx += THREADS) {
            int r = idx / (BK / 8);
            int c = (idx % (BK / 8)) * 8;
            int gr = row0 + r;
            uint4 vh = z4, vl = z4;
            if (gr < M) {
                vh = *(const uint4*)(Ah + (size_t)gr * K + k0 + c);
                vl = *(const uint4*)(Al + (size_t)gr * K + k0 + c);
            }
            *(uint4*)&sA[r * AST + c] = vh;
            *(uint4*)&sA[ALO + r * AST + c] = vl;
        }
        // load B tile (transposed weights [N][K])
        #pragma unroll
        for (int idx = tid; idx < BN * (BK / 8); idx += THREADS) {
            int r = idx / (BK / 8);
            int c = (idx % (BK / 8)) * 8;
            *(uint4*)&sB[r * AST + c] = *(const uint4*)(Bh + (size_t)(n0 + r) * K + k0 + c);
            *(uint4*)&sB[BLO + r * AST + c] = *(const uint4*)(Bl + (size_t)(n0 + r) * K + k0 + c);
        }
        __syncthreads();

        #pragma unroll
        for (int kk = 0; kk < BK; kk += 16) {
            uint32_t ah[MT][4], al[MT][4];
            #pragma unroll
            for (int mt = 0; mt < MT; mt++) {
                int r = wm * WM + mt * 16 + gid;
                ah[mt][0] = *(const uint32_t*)&sA[r * AST + kk + 2 * tig];
                ah[mt][1] = *(const uint32_t*)&sA[(r + 8) * AST + kk + 2 * tig];
                ah[mt][2] = *(const uint32_t*)&sA[r * AST + kk + 8 + 2 * tig];
                ah[mt][3] = *(const uint32_t*)&sA[(r + 8) * AST + kk + 8 + 2 * tig];
                al[mt][0] = *(const uint32_t*)&sA[ALO + r * AST + kk + 2 * tig];
                al[mt][1] = *(const uint32_t*)&sA[ALO + (r + 8) * AST + kk + 2 * tig];
                al[mt][2] = *(const uint32_t*)&sA[ALO + r * AST + kk + 8 + 2 * tig];
                al[mt][3] = *(const uint32_t*)&sA[ALO + (r + 8) * AST + kk + 8 + 2 * tig];
            }
            #pragma unroll
            for (int nt = 0; nt < NT; nt++) {
                int bn = wn * WN + nt * 8 + gid;
                uint32_t bh0 = *(const uint32_t*)&sB[bn * AST + kk + 2 * tig];
                uint32_t bh1 = *(const uint32_t*)&sB[bn * AST + kk + 8 + 2 * tig];
                uint32_t bl0 = *(const uint32_t*)&sB[BLO + bn * AST + kk + 2 * tig];
                uint32_t bl1 = *(const uint32_t*)&sB[BLO + bn * AST + kk + 8 + 2 * tig];
                #pragma unroll
                for (int mt = 0; mt < MT; mt++) {
                    mma16816(acc[mt][nt], ah[mt], bh0, bh1);
                    mma16816(acc[mt][nt], ah[mt], bl0, bl1);
                    mma16816(acc[mt][nt], al[mt], bh0, bh1);
                }
            }
        }
        __syncthreads();
    }

    // store
    #pragma unroll
    for (int mt = 0; mt < MT; mt++) {
        #pragma unroll
        for (int nt = 0; nt < NT; nt++) {
            int gr = row0 + wm * WM + mt * 16 + gid;
            int gc = n0 + wn * WN + nt * 8 + 2 * tig;
            if (gr < M)
                *(float2*)&C[(size_t)gr * N + gc] = make_float2(acc[mt][nt][0], acc[mt][nt][1]);
            if (gr + 8 < M)
                *(float2*)&C[(size_t)(gr + 8) * N + gc] = make_float2(acc[mt][nt][2], acc[mt][nt][3]);
        }
    }
}

// ---------------- GAT layer 1: warp per dst node, online softmax ----------------
// Writes h1 directly as split bf16 for the layer-2 tensor GEMMs.
__global__ void gat1_kernel(const float* __restrict__ att, const float* __restrict__ bias,
                            int n) {
    int warp = (blockIdx.x * blockDim.x + threadIdx.x) >> 5;
    int lane = threadIdx.x & 31;
    if (warp >= n) return;
    int head = lane >> 2, sub = lane & 3;

    const float4* xr4 = (const float4*)(g_xr1 + (size_t)warp * H1DIM + lane * 8);
    float4 r0 = xr4[0], r1 = xr4[1];
    float xrv[8] = {r0.x, r0.y, r0.z, r0.w, r1.x, r1.y, r1.z, r1.w};
    float av[8];
    #pragma unroll
    for (int k = 0; k < 8; k++) av[k] = att[head * HID + sub * 8 + k];

    float acc[8] = {0.f, 0.f, 0.f, 0.f, 0.f, 0.f, 0.f, 0.f};
    float m = -1e30f, denom = 0.f;

    int s = g_rowstart[warp], e = g_rowstart[warp + 1];
    for (int j = s; j < e; j++) {
        int src = g_col[j];
        const float4* p4 = (const float4*)(g_xl1 + (size_t)src * H1DIM + lane * 8);
        float4 a = p4[0], b = p4[1];
        float xv[8] = {a.x, a.y, a.z, a.w, b.x, b.y, b.z, b.w};
        float logit = 0.f;
        #pragma unroll
        for (int k = 0; k < 8; k++) {
            float t = xv[k] + xrv[k];
            t = t > 0.f ? t : NEG_SLOPE * t;
            logit += t * av[k];
        }
        logit += __shfl_xor_sync(0xFFFFFFFFu, logit, 1);
        logit += __shfl_xor_sync(0xFFFFFFFFu, logit, 2);
        float mn = fmaxf(m, logit);
        float sc = __expf(m - mn);
        float w  = __expf(logit - mn);
        denom = denom * sc + w;
        #pragma unroll
        for (int k = 0; k < 8; k++) acc[k] = acc[k] * sc + w * xv[k];
        m = mn;
    }
    float inv = 1.f / fmaxf(denom, 1e-16f);
    uint16_t hv[8], lv[8];
    #pragma unroll
    for (int k = 0; k < 8; k++) {
        float v = acc[k] * inv + bias[lane * 8 + k];
        v = v > 0.f ? v : expm1f(v);      // ELU
        split_bf16(v, hv[k], lv[k]);
    }
    *(uint4*)&g_h1h[(size_t)warp * H1DIM + lane * 8] = *(const uint4*)hv;
    *(uint4*)&g_h1l[(size_t)warp * H1DIM + lane * 8] = *(const uint4*)lv;
}

// ---------------- GAT layer 2 (1 head) + fused final linear ----------------
__global__ void gat2_kernel(const float* __restrict__ att, const float* __restrict__ bias,
                            const float* __restrict__ Wlin, const float* __restrict__ blin,
                            float* __restrict__ out, int n) {
    __shared__ float sh[8][HID];
    int warp = (blockIdx.x * blockDim.x + threadIdx.x) >> 5;
    int lane = threadIdx.x & 31;
    int wl = threadIdx.x >> 5;
    if (warp >= n) return;

    float xrv = g_xr2[(size_t)warp * HID + lane];
    float av  = att[lane];
    float acc = 0.f, m = -1e30f, denom = 0.f;

    int s = g_rowstart[warp], e = g_rowstart[warp + 1];
    for (int j = s; j < e; j++) {
        int src = g_col[j];
        float xv = g_xl2[(size_t)src * HID + lane];
        float t = xv + xrv;
        t = t > 0.f ? t : NEG_SLOPE * t;
        float logit = t * av;
        #pragma unroll
        for (int d = 16; d >= 1; d >>= 1) logit += __shfl_xor_sync(0xFFFFFFFFu, logit, d);
        float mn = fmaxf(m, logit);
        float sc = __expf(m - mn);
        float w  = __expf(logit - mn);
        denom = denom * sc + w;
        acc = acc * sc + w * xv;
        m = mn;
    }
    float h2 = acc / fmaxf(denom, 1e-16f) + bias[lane];
    h2 = h2 > 0.f ? h2 : expm1f(h2);          // ELU

    sh[wl][lane] = h2;
    __syncwarp();
    if (lane < OUTD) {
        float sum = blin[lane];
        #pragma unroll
        for (int c = 0; c < HID; c++) sum += sh[wl][c] * Wlin[c * OUTD + lane];
        out[(size_t)warp * OUTD + lane] = sum;
    }
}

// ---------------- launch (kernel launches ONLY — fully capturable) ----------------
extern "C" void kernel_launch(void* const* d_in, const int* in_sizes, int n_in,
                              void* d_out, int out_size) {
    const float* x    = (const float*)d_in[0];
    const int*   ei   = (const int*)d_in[1];     // int32 (JAX x64 disabled)
    const float* W1l  = (const float*)d_in[2];
    const float* W1r  = (const float*)d_in[3];
    const float* att1 = (const float*)d_in[4];
    const float* b1   = (const float*)d_in[5];
    const float* W2l  = (const float*)d_in[6];
    const float* W2r  = (const float*)d_in[7];
    const float* att2 = (const float*)d_in[8];
    const float* b2   = (const float*)d_in[9];
    const float* Wlin = (const float*)d_in[10];
    const float* blin = (const float*)d_in[11];
    float* out = (float*)d_out;

    int N = in_sizes[0] / D_IN;
    int E = in_sizes[1] / 2;

    // --- CSR build (by destination) ---
    zero_counts_kernel<<<(N + 255) / 256, 256>>>(N);
    hist_kernel<<<(E + 255) / 256, 256>>>(ei, E, N);
    scan_kernel<<<1, 1024>>>(N);
    scatter_kernel<<<(E + N + 255) / 256, 256>>>(ei, E, N);

    // --- operand conversion (runs concurrently-independent of CSR) ---
    split_x_kernel<<<(N * D_IN + 255) / 256, 256>>>(x, N * D_IN);
    {
        dim3 g(64, 4);
        split_w_kernel<<<g, 256>>>(W1l, W1r, W2l, W2r);
    }

    // --- layer-1 transforms: xl1 = x@W1l, xr1 = x@W1r  (tensor cores, bf16x3) ---
    {
        dim3 grid(H1DIM / 128, (N + 127) / 128);
        mma_gemm_kernel<128, 128, 32, 32, 64><<<grid, 256>>>(N, H1DIM, D_IN, 0, 0, 0);
        mma_gemm_kernel<128, 128, 32, 32, 64><<<grid, 256>>>(N, H1DIM, D_IN, 0, 1, 1);
    }

    // --- GAT layer 1 (warp per node) ---
    gat1_kernel<<<(N * 32 + 255) / 256, 256>>>(att1, b1, N);

    // --- layer-2 transforms: xl2 = h1@W2l, xr2 = h1@W2r ---
    {
        dim3 grid(HID / 32, (N + 127) / 128);
        mma_gemm_kernel<128, 32, 32, 32, 16><<<grid, 256>>>(N, HID, H1DIM, 1, 2, 2);
        mma_gemm_kernel<128, 32, 32, 32, 16><<<grid, 256>>>(N, HID, H1DIM, 1, 3, 3);
    }

    // --- GAT layer 2 + final linear ---
    gat2_kernel<<<(N * 32 + 255) / 256, 256>>>(att2, b2, Wlin, blin, out, N);
}

// round 10
// speedup vs baseline: 1.4267x; 1.1336x over previous
#include <cuda_runtime.h>
#include <cuda_bf16.h>
#include <cstdint>
#include <math.h>

// Problem constants (fixed by the dataset)
#define MAX_N 50000
#define MAX_E 400000
#define D_IN 128
#define HID 32
#define HEADS 8
#define H1DIM (HEADS * HID)   // 256
#define T1W (2 * H1DIM)       // 512: [xl1 | xr1] concatenated per row
#define T2W (2 * HID)         // 64:  [xl2 | xr2]
#define OUTD 16
#define NEG_SLOPE 0.2f

// ---------------- static scratch (no allocations allowed) ----------------
__device__ float g_t1[(size_t)MAX_N * T1W];   // layer-1 GEMM output [xl|xr]
__device__ float g_t2[(size_t)MAX_N * T2W];   // layer-2 GEMM output [xl|xr]
// split-bf16 operands (raw u16)
__device__ __align__(16) uint16_t g_xh [(size_t)MAX_N * D_IN];
__device__ __align__(16) uint16_t g_xlo[(size_t)MAX_N * D_IN];
__device__ __align__(16) uint16_t g_h1h[(size_t)MAX_N * H1DIM];
__device__ __align__(16) uint16_t g_h1l[(size_t)MAX_N * H1DIM];
// weights: split + transposed + CONCATENATED: [Ntot][K]
__device__ __align__(16) uint16_t g_w1h[T1W * D_IN],  g_w1lo[T1W * D_IN];
__device__ __align__(16) uint16_t g_w2h[T2W * H1DIM], g_w2lo[T2W * H1DIM];
// CSR
__device__ int g_counts[MAX_N];
__device__ int g_cursor[MAX_N];
__device__ int g_rowstart[MAX_N + 1];
__device__ int g_col[MAX_E + MAX_N];

// ---------------- helpers ----------------
__device__ __forceinline__ void split_bf16(float f, uint16_t& hi, uint16_t& lo) {
    __nv_bfloat16 h = __float2bfloat16_rn(f);
    __nv_bfloat16 l = __float2bfloat16_rn(f - __bfloat162float(h));
    hi = __bfloat16_as_ushort(h);
    lo = __bfloat16_as_ushort(l);
}

__device__ __forceinline__ void mma16816(float* c, const uint32_t* a, uint32_t b0, uint32_t b1) {
    asm volatile(
        "mma.sync.aligned.m16n8k16.row.col.f32.bf16.bf16.f32 "
        "{%0,%1,%2,%3}, {%4,%5,%6,%7}, {%8,%9}, {%0,%1,%2,%3};"
        : "+f"(c[0]), "+f"(c[1]), "+f"(c[2]), "+f"(c[3])
        : "r"(a[0]), "r"(a[1]), "r"(a[2]), "r"(a[3]), "r"(b0), "r"(b1));
}

__device__ __forceinline__ void cpa16(uint16_t* dst, const uint16_t* src, bool valid) {
    uint32_t s = (uint32_t)__cvta_generic_to_shared(dst);
    int sz = valid ? 16 : 0;
    asm volatile("cp.async.ca.shared.global [%0], [%1], 16, %2;" :: "r"(s), "l"(src), "r"(sz));
}
#define CP_COMMIT() asm volatile("cp.async.commit_group;")
#define CP_WAIT(n)  asm volatile("cp.async.wait_group %0;" :: "n"(n))

// ---------------- CSR build ----------------
__global__ void zero_counts_kernel(int n) {
    int t = blockIdx.x * blockDim.x + threadIdx.x;
    if (t < n) g_counts[t] = 0;
}

// edge_index is int32 (JAX x64 disabled downcasts the reference's int64)
__global__ void hist_kernel(const int* __restrict__ ei, int E, int N) {
    int t = blockIdx.x * blockDim.x + threadIdx.x;
    if (t < E) {
        int d = ei[E + t];
        if ((unsigned)d < (unsigned)N) atomicAdd(&g_counts[d], 1);
    }
}

__global__ void scan_kernel(int n) {
    __shared__ int warp_sums[32];
    __shared__ int carry_s;
    int tid = threadIdx.x;
    int lane = tid & 31, wid = tid >> 5;
    if (tid == 0) carry_s = 0;
    __syncthreads();
    for (int base = 0; base < n; base += 1024) {
        int i = base + tid;
        int v = (i < n) ? g_counts[i] + 1 : 0;
        int x = v;
        #pragma unroll
        for (int d = 1; d < 32; d <<= 1) {
            int t = __shfl_up_sync(0xFFFFFFFFu, x, d);
            if (lane >= d) x += t;
        }
        if (lane == 31) warp_sums[wid] = x;
        __syncthreads();
        if (tid < 32) {
            int w = warp_sums[tid];
            #pragma unroll
            for (int d = 1; d < 32; d <<= 1) {
                int t = __shfl_up_sync(0xFFFFFFFFu, w, d);
                if (tid >= d) w += t;
            }
            warp_sums[tid] = w;
        }
        __syncthreads();
        int blockIncl = x + (wid > 0 ? warp_sums[wid - 1] : 0);
        int carry = carry_s;
        int total = warp_sums[31];
        int excl = carry + blockIncl - v;
        if (i < n) { g_rowstart[i] = excl; g_cursor[i] = excl; }
        __syncthreads();
        if (tid == 0) carry_s += total;
        __syncthreads();
    }
    if (tid == 0) g_rowstart[n] = carry_s;
}

__global__ void scatter_kernel(const int* __restrict__ ei, int E, int N) {
    int t = blockIdx.x * blockDim.x + threadIdx.x;
    if (t < E) {
        int d = ei[E + t];
        int s = ei[t];
        if ((unsigned)d < (unsigned)N && (unsigned)s < (unsigned)N) {
            int slot = atomicAdd(&g_cursor[d], 1);
            g_col[slot] = s;
        }
    } else if (t < E + N) {
        int i = t - E;
        int slot = atomicAdd(&g_cursor[i], 1);
        g_col[slot] = i;
    }
}

// ---------------- conversions ----------------
__global__ void split_x_kernel(const float* __restrict__ x, int total) {
    int t = blockIdx.x * blockDim.x + threadIdx.x;
    if (t < total) {
        uint16_t hi, lo;
        split_bf16(x[t], hi, lo);
        g_xh[t] = hi;
        g_xlo[t] = lo;
    }
}

// split + transpose + concat weights: W[K][N] f32 -> Wt[roff+n][k] bf16 hi/lo
__global__ void split_w_kernel(const float* __restrict__ W1l, const float* __restrict__ W1r,
                               const float* __restrict__ W2l, const float* __restrict__ W2r) {
    int m = blockIdx.y;
    const float* src; uint16_t *dh, *dl; int K, N, roff;
    if (m == 0)      { src = W1l; dh = g_w1h; dl = g_w1lo; K = D_IN;  N = H1DIM; roff = 0; }
    else if (m == 1) { src = W1r; dh = g_w1h; dl = g_w1lo; K = D_IN;  N = H1DIM; roff = H1DIM; }
    else if (m == 2) { src = W2l; dh = g_w2h; dl = g_w2lo; K = H1DIM; N = HID; roff = 0; }
    else             { src = W2r; dh = g_w2h; dl = g_w2lo; K = H1DIM; N = HID; roff = HID; }
    int total = K * N;
    for (int t = blockIdx.x * blockDim.x + threadIdx.x; t < total; t += gridDim.x * blockDim.x) {
        int k = t / N, n = t % N;
        uint16_t hi, lo;
        split_bf16(src[t], hi, lo);
        dh[(size_t)(roff + n) * K + k] = hi;
        dl[(size_t)(roff + n) * K + k] = lo;
    }
}

// ---------------- bf16x3 tensor-core GEMM, cp.async double-buffered ----------------
// C[M,Ntot] = A[M,K] @ W[K,Ntot] via Ah*Bh + Ah*Bl + Al*Bh.
// asel: 0 = x split, 1 = h1 split.  lay: 0 = (w1, g_t1), 1 = (w2, g_t2).
template <int BM, int BN, int BK, int WM, int WN>
__global__ void __launch_bounds__((BM / WM) * (BN / WN) * 32)
mma_gemm_db_kernel(int M, int Ntot, int K, int asel, int lay) {
    constexpr int WARPS_M = BM / WM;
    constexpr int WARPS_N = BN / WN;
    constexpr int THREADS = WARPS_M * WARPS_N * 32;
    constexpr int MT = WM / 16;
    constexpr int NT = WN / 8;
    constexpr int AST = BK + 8;           // conflict-free fragment stride
    constexpr int A_SZ = BM * AST;        // u16 per (hi or lo)
    constexpr int B_SZ = BN * AST;
    constexpr int STAGE = 2 * A_SZ + 2 * B_SZ;

    extern __shared__ uint16_t sm[];

    const uint16_t* Ah = asel == 0 ? g_xh  : g_h1h;
    const uint16_t* Al = asel == 0 ? g_xlo : g_h1l;
    const uint16_t* Bh = lay == 0 ? g_w1h  : g_w2h;
    const uint16_t* Bl = lay == 0 ? g_w1lo : g_w2lo;
    float* C = lay == 0 ? g_t1 : g_t2;

    int tid = threadIdx.x;
    int wid = tid >> 5, lane = tid & 31;
    int gid = lane >> 2, tig = lane & 3;
    int wm = wid / WARPS_N, wn = wid % WARPS_N;
    int row0 = blockIdx.y * BM;
    int n0 = blockIdx.x * BN;

    float acc[MT][NT][4];
    #pragma unroll
    for (int i = 0; i < MT; i++)
        #pragma unroll
        for (int j = 0; j < NT; j++)
            #pragma unroll
            for (int q = 0; q < 4; q++) acc[i][j][q] = 0.f;

    const int T = K / BK;

    auto load_stage = [&](int s, int k0) {
        uint16_t* base = sm + s * STAGE;
        #pragma unroll
        for (int idx = tid; idx < BM * (BK / 8); idx += THREADS) {
            int r = idx / (BK / 8);
            int c = (idx % (BK / 8)) * 8;
            int gr = row0 + r;
            bool v = gr < M;
            size_t off = (size_t)(v ? gr : 0) * K + k0 + c;
            cpa16(base + r * AST + c, Ah + off, v);
            cpa16(base + A_SZ + r * AST + c, Al + off, v);
        }
        #pragma unroll
        for (int idx = tid; idx < BN * (BK / 8); idx += THREADS) {
            int r = idx / (BK / 8);
            int c = (idx % (BK / 8)) * 8;
            size_t off = (size_t)(n0 + r) * K + k0 + c;
            cpa16(base + 2 * A_SZ + r * AST + c, Bh + off, true);
            cpa16(base + 2 * A_SZ + B_SZ + r * AST + c, Bl + off, true);
        }
        CP_COMMIT();
    };

    load_stage(0, 0);
    for (int i = 0; i < T; i++) {
        if (i + 1 < T) {
            load_stage((i + 1) & 1, (i + 1) * BK);
            CP_WAIT(1);
        } else {
            CP_WAIT(0);
        }
        __syncthreads();

        const uint16_t* sAh = sm + (i & 1) * STAGE;
        const uint16_t* sAl = sAh + A_SZ;
        const uint16_t* sBh = sAh + 2 * A_SZ;
        const uint16_t* sBl = sBh + B_SZ;

        #pragma unroll
        for (int kk = 0; kk < BK; kk += 16) {
            uint32_t ah[MT][4], al[MT][4];
            #pragma unroll
            for (int mt = 0; mt < MT; mt++) {
                int r = wm * WM + mt * 16 + gid;
                ah[mt][0] = *(const uint32_t*)&sAh[r * AST + kk + 2 * tig];
                ah[mt][1] = *(const uint32_t*)&sAh[(r + 8) * AST + kk + 2 * tig];
                ah[mt][2] = *(const uint32_t*)&sAh[r * AST + kk + 8 + 2 * tig];
                ah[mt][3] = *(const uint32_t*)&sAh[(r + 8) * AST + kk + 8 + 2 * tig];
                al[mt][0] = *(const uint32_t*)&sAl[r * AST + kk + 2 * tig];
                al[mt][1] = *(const uint32_t*)&sAl[(r + 8) * AST + kk + 2 * tig];
                al[mt][2] = *(const uint32_t*)&sAl[r * AST + kk + 8 + 2 * tig];
                al[mt][3] = *(const uint32_t*)&sAl[(r + 8) * AST + kk + 8 + 2 * tig];
            }
            #pragma unroll
            for (int nt = 0; nt < NT; nt++) {
                int bn = wn * WN + nt * 8 + gid;
                uint32_t bh0 = *(const uint32_t*)&sBh[bn * AST + kk + 2 * tig];
                uint32_t bh1 = *(const uint32_t*)&sBh[bn * AST + kk + 8 + 2 * tig];
                uint32_t bl0 = *(const uint32_t*)&sBl[bn * AST + kk + 2 * tig];
                uint32_t bl1 = *(const uint32_t*)&sBl[bn * AST + kk + 8 + 2 * tig];
                #pragma unroll
                for (int mt = 0; mt < MT; mt++) {
                    mma16816(acc[mt][nt], ah[mt], bh0, bh1);
                    mma16816(acc[mt][nt], ah[mt], bl0, bl1);
                    mma16816(acc[mt][nt], al[mt], bh0, bh1);
                }
            }
        }
        __syncthreads();
    }

    #pragma unroll
    for (int mt = 0; mt < MT; mt++) {
        #pragma unroll
        for (int nt = 0; nt < NT; nt++) {
            int gr = row0 + wm * WM + mt * 16 + gid;
            int gc = n0 + wn * WN + nt * 8 + 2 * tig;
            if (gr < M)
                *(float2*)&C[(size_t)gr * Ntot + gc] = make_float2(acc[mt][nt][0], acc[mt][nt][1]);
            if (gr + 8 < M)
                *(float2*)&C[(size_t)(gr + 8) * Ntot + gc] = make_float2(acc[mt][nt][2], acc[mt][nt][3]);
        }
    }
}

// ---------------- GAT layer 1: warp per dst node, online softmax (1 exp/edge) ----------------
__global__ void gat1_kernel(const float* __restrict__ att, const float* __restrict__ bias,
                            int n) {
    int warp = (blockIdx.x * blockDim.x + threadIdx.x) >> 5;
    int lane = threadIdx.x & 31;
    if (warp >= n) return;
    int head = lane >> 2, sub = lane & 3;

    const float4* xr4 = (const float4*)(g_t1 + (size_t)warp * T1W + H1DIM + lane * 8);
    float4 r0 = xr4[0], r1 = xr4[1];
    float xrv[8] = {r0.x, r0.y, r0.z, r0.w, r1.x, r1.y, r1.z, r1.w};
    float av[8];
    #pragma unroll
    for (int k = 0; k < 8; k++) av[k] = att[head * HID + sub * 8 + k];

    float acc[8] = {0.f, 0.f, 0.f, 0.f, 0.f, 0.f, 0.f, 0.f};
    float m = -1e30f, denom = 0.f;

    int s = g_rowstart[warp], e = g_rowstart[warp + 1];
    for (int j = s; j < e; j++) {
        int src = g_col[j];
        const float4* p4 = (const float4*)(g_t1 + (size_t)src * T1W + lane * 8);
        float4 a = p4[0], b = p4[1];
        float xv[8] = {a.x, a.y, a.z, a.w, b.x, b.y, b.z, b.w};
        float logit = 0.f;
        #pragma unroll
        for (int k = 0; k < 8; k++) {
            float t = xv[k] + xrv[k];
            t = t > 0.f ? t : NEG_SLOPE * t;
            logit += t * av[k];
        }
        logit += __shfl_xor_sync(0xFFFFFFFFu, logit, 1);
        logit += __shfl_xor_sync(0xFFFFFFFFu, logit, 2);
        // one exp: exactly one of (sc, w) is exp(-|logit-m|), the other 1
        float ex = __expf(-fabsf(logit - m));
        bool keep = logit <= m;
        float sc = keep ? 1.f : ex;
        float w  = keep ? ex : 1.f;
        m = fmaxf(m, logit);
        denom = denom * sc + w;
        #pragma unroll
        for (int k = 0; k < 8; k++) acc[k] = acc[k] * sc + w * xv[k];
    }
    float inv = 1.f / fmaxf(denom, 1e-16f);
    uint16_t hv[8], lv[8];
    #pragma unroll
    for (int k = 0; k < 8; k++) {
        float v = acc[k] * inv + bias[lane * 8 + k];
        v = v > 0.f ? v : expm1f(v);      // ELU
        split_bf16(v, hv[k], lv[k]);
    }
    *(uint4*)&g_h1h[(size_t)warp * H1DIM + lane * 8] = *(const uint4*)hv;
    *(uint4*)&g_h1l[(size_t)warp * H1DIM + lane * 8] = *(const uint4*)lv;
}

// ---------------- GAT layer 2 (1 head) + fused final linear ----------------
__global__ void gat2_kernel(const float* __restrict__ att, const float* __restrict__ bias,
                            const float* __restrict__ Wlin, const float* __restrict__ blin,
                            float* __restrict__ out, int n) {
    __shared__ float sh[8][HID];
    int warp = (blockIdx.x * blockDim.x + threadIdx.x) >> 5;
    int lane = threadIdx.x & 31;
    int wl = threadIdx.x >> 5;
    if (warp >= n) return;

    float xrv = g_t2[(size_t)warp * T2W + HID + lane];
    float av  = att[lane];
    float acc = 0.f, m = -1e30f, denom = 0.f;

    int s = g_rowstart[warp], e = g_rowstart[warp + 1];
    for (int j = s; j < e; j++) {
        int src = g_col[j];
        float xv = g_t2[(size_t)src * T2W + lane];
        float t = xv + xrv;
        t = t > 0.f ? t : NEG_SLOPE * t;
        float logit = t * av;
        #pragma unroll
        for (int d = 16; d >= 1; d >>= 1) logit += __shfl_xor_sync(0xFFFFFFFFu, logit, d);
        float ex = __expf(-fabsf(logit - m));
        bool keep = logit <= m;
        float sc = keep ? 1.f : ex;
        float w  = keep ? ex : 1.f;
        m = fmaxf(m, logit);
        denom = denom * sc + w;
        acc = acc * sc + w * xv;
    }
    float h2 = acc / fmaxf(denom, 1e-16f) + bias[lane];
    h2 = h2 > 0.f ? h2 : expm1f(h2);          // ELU

    sh[wl][lane] = h2;
    __syncwarp();
    if (lane < OUTD) {
        float sum = blin[lane];
        #pragma unroll
        for (int c = 0; c < HID; c++) sum += sh[wl][c] * Wlin[c * OUTD + lane];
        out[(size_t)warp * OUTD + lane] = sum;
    }
}

// ---------------- launch ----------------
extern "C" void kernel_launch(void* const* d_in, const int* in_sizes, int n_in,
                              void* d_out, int out_size) {
    const float* x    = (const float*)d_in[0];
    const int*   ei   = (const int*)d_in[1];     // int32 (JAX x64 disabled)
    const float* W1l  = (const float*)d_in[2];
    const float* W1r  = (const float*)d_in[3];
    const float* att1 = (const float*)d_in[4];
    const float* b1   = (const float*)d_in[5];
    const float* W2l  = (const float*)d_in[6];
    const float* W2r  = (const float*)d_in[7];
    const float* att2 = (const float*)d_in[8];
    const float* b2   = (const float*)d_in[9];
    const float* Wlin = (const float*)d_in[10];
    const float* blin = (const float*)d_in[11];
    float* out = (float*)d_out;

    int N = in_sizes[0] / D_IN;
    int E = in_sizes[1] / 2;

    // dynamic smem opt-in (idempotent; not a stream op — capture-safe)
    cudaFuncSetAttribute(mma_gemm_db_kernel<128, 128, 32, 32, 64>,
                         cudaFuncAttributeMaxDynamicSharedMemorySize, 81920);
    cudaFuncSetAttribute(mma_gemm_db_kernel<128, 64, 32, 32, 32>,
                         cudaFuncAttributeMaxDynamicSharedMemorySize, 61440);

    // --- CSR build (by destination) ---
    zero_counts_kernel<<<(N + 255) / 256, 256>>>(N);
    hist_kernel<<<(E + 255) / 256, 256>>>(ei, E, N);
    scan_kernel<<<1, 1024>>>(N);
    scatter_kernel<<<(E + N + 255) / 256, 256>>>(ei, E, N);

    // --- operand conversion ---
    split_x_kernel<<<(N * D_IN + 255) / 256, 256>>>(x, N * D_IN);
    {
        dim3 g(64, 4);
        split_w_kernel<<<g, 256>>>(W1l, W1r, W2l, W2r);
    }

    // --- layer-1 transform (fused): t1 = x @ [W1l|W1r] ---
    {
        dim3 grid(T1W / 128, (N + 127) / 128);
        mma_gemm_db_kernel<128, 128, 32, 32, 64><<<grid, 256, 81920>>>(N, T1W, D_IN, 0, 0);
    }

    // --- GAT layer 1 (warp per node) ---
    gat1_kernel<<<(N * 32 + 255) / 256, 256>>>(att1, b1, N);

    // --- layer-2 transform (fused): t2 = h1 @ [W2l|W2r] ---
    {
        dim3 grid(T2W / 64, (N + 127) / 128);
        mma_gemm_db_kernel<128, 64, 32, 32, 32><<<grid, 256, 61440>>>(N, T2W, H1DIM, 1, 1);
    }

    // --- GAT layer 2 + final linear ---
    gat2_kernel<<<(N * 32 + 255) / 256, 256>>>(att2, b2, Wlin, blin, out, N);
}

// round 14
// speedup vs baseline: 1.7506x; 1.2270x over previous
#include <cuda_runtime.h>
#include <cuda_bf16.h>
#include <cstdint>
#include <math.h>

// Problem constants (fixed by the dataset)
#define MAX_N 50000
#define MAX_E 400000
#define D_IN 128
#define HID 32
#define HEADS 8
#define H1DIM (HEADS * HID)   // 256
#define T1W (2 * H1DIM)       // 512: [xl1 | xr1] concatenated per row
#define T2W (2 * HID)         // 64:  [xl2 | xr2]
#define OUTD 16
#define NEG_SLOPE 0.2f

// ---------------- static scratch (no allocations allowed) ----------------
__device__ float g_t1[(size_t)MAX_N * T1W];   // layer-1 GEMM output [xl|xr]
__device__ float g_t2[(size_t)MAX_N * T2W];   // layer-2 GEMM output [xl|xr]
// split-bf16 operands (raw u16)
__device__ __align__(16) uint16_t g_xh [(size_t)MAX_N * D_IN];
__device__ __align__(16) uint16_t g_xlo[(size_t)MAX_N * D_IN];
__device__ __align__(16) uint16_t g_h1h[(size_t)MAX_N * H1DIM];
__device__ __align__(16) uint16_t g_h1l[(size_t)MAX_N * H1DIM];
// weights: split + transposed + CONCATENATED: [Ntot][K]
__device__ __align__(16) uint16_t g_w1h[T1W * D_IN],  g_w1lo[T1W * D_IN];
__device__ __align__(16) uint16_t g_w2h[T2W * H1DIM], g_w2lo[T2W * H1DIM];
// CSR
__device__ int g_counts[MAX_N];
__device__ int g_cursor[MAX_N];
__device__ int g_rowstart[MAX_N + 1];
__device__ int g_col[MAX_E + MAX_N];

// ---------------- helpers ----------------
__device__ __forceinline__ void split_bf16(float f, uint16_t& hi, uint16_t& lo) {
    __nv_bfloat16 h = __float2bfloat16_rn(f);
    __nv_bfloat16 l = __float2bfloat16_rn(f - __bfloat162float(h));
    hi = __bfloat16_as_ushort(h);
    lo = __bfloat16_as_ushort(l);
}

__device__ __forceinline__ void mma16816(float* c, const uint32_t* a, uint32_t b0, uint32_t b1) {
    asm volatile(
        "mma.sync.aligned.m16n8k16.row.col.f32.bf16.bf16.f32 "
        "{%0,%1,%2,%3}, {%4,%5,%6,%7}, {%8,%9}, {%0,%1,%2,%3};"
        : "+f"(c[0]), "+f"(c[1]), "+f"(c[2]), "+f"(c[3])
        : "r"(a[0]), "r"(a[1]), "r"(a[2]), "r"(a[3]), "r"(b0), "r"(b1));
}

// streamed (L2-only) async copy — for A tiles read once
__device__ __forceinline__ void cpa16_cg(uint16_t* dst, const uint16_t* src, bool valid) {
    uint32_t s = (uint32_t)__cvta_generic_to_shared(dst);
    int sz = valid ? 16 : 0;
    asm volatile("cp.async.cg.shared.global [%0], [%1], 16, %2;" :: "r"(s), "l"(src), "r"(sz));
}
// cached async copy — for B (weight) tiles reused across CTAs
__device__ __forceinline__ void cpa16_ca(uint16_t* dst, const uint16_t* src) {
    uint32_t s = (uint32_t)__cvta_generic_to_shared(dst);
    asm volatile("cp.async.ca.shared.global [%0], [%1], 16;" :: "r"(s), "l"(src));
}
#define CP_COMMIT() asm volatile("cp.async.commit_group;")
#define CP_WAIT(n)  asm volatile("cp.async.wait_group %0;" :: "n"(n))

// ---------------- CSR build ----------------
__global__ void zero_counts_kernel(int n) {
    int t = blockIdx.x * blockDim.x + threadIdx.x;
    if (t < n) g_counts[t] = 0;
}

// edge_index is int32 (JAX x64 disabled downcasts the reference's int64)
__global__ void hist_kernel(const int* __restrict__ ei, int E, int N) {
    int t = blockIdx.x * blockDim.x + threadIdx.x;
    if (t < E) {
        int d = ei[E + t];
        if ((unsigned)d < (unsigned)N) atomicAdd(&g_counts[d], 1);
    }
}

__global__ void scan_kernel(int n) {
    __shared__ int warp_sums[32];
    __shared__ int carry_s;
    int tid = threadIdx.x;
    int lane = tid & 31, wid = tid >> 5;
    if (tid == 0) carry_s = 0;
    __syncthreads();
    for (int base = 0; base < n; base += 1024) {
        int i = base + tid;
        int v = (i < n) ? g_counts[i] + 1 : 0;
        int x = v;
        #pragma unroll
        for (int d = 1; d < 32; d <<= 1) {
            int t = __shfl_up_sync(0xFFFFFFFFu, x, d);
            if (lane >= d) x += t;
        }
        if (lane == 31) warp_sums[wid] = x;
        __syncthreads();
        if (tid < 32) {
            int w = warp_sums[tid];
            #pragma unroll
            for (int d = 1; d < 32; d <<= 1) {
                int t = __shfl_up_sync(0xFFFFFFFFu, w, d);
                if (tid >= d) w += t;
            }
            warp_sums[tid] = w;
        }
        __syncthreads();
        int blockIncl = x + (wid > 0 ? warp_sums[wid - 1] : 0);
        int carry = carry_s;
        int total = warp_sums[31];
        int excl = carry + blockIncl - v;
        if (i < n) { g_rowstart[i] = excl; g_cursor[i] = excl; }
        __syncthreads();
        if (tid == 0) carry_s += total;
        __syncthreads();
    }
    if (tid == 0) g_rowstart[n] = carry_s;
}

__global__ void scatter_kernel(const int* __restrict__ ei, int E, int N) {
    int t = blockIdx.x * blockDim.x + threadIdx.x;
    if (t < E) {
        int d = ei[E + t];
        int s = ei[t];
        if ((unsigned)d < (unsigned)N && (unsigned)s < (unsigned)N) {
            int slot = atomicAdd(&g_cursor[d], 1);
            g_col[slot] = s;
        }
    } else if (t < E + N) {
        int i = t - E;
        int slot = atomicAdd(&g_cursor[i], 1);
        g_col[slot] = i;
    }
}

// ---------------- conversions ----------------
__global__ void split_x_kernel(const float* __restrict__ x, int total) {
    int t = blockIdx.x * blockDim.x + threadIdx.x;
    if (t < total) {
        uint16_t hi, lo;
        split_bf16(x[t], hi, lo);
        g_xh[t] = hi;
        g_xlo[t] = lo;
    }
}

// split + transpose + concat weights: W[K][N] f32 -> Wt[roff+n][k] bf16 hi/lo
__global__ void split_w_kernel(const float* __restrict__ W1l, const float* __restrict__ W1r,
                               const float* __restrict__ W2l, const float* __restrict__ W2r) {
    int m = blockIdx.y;
    const float* src; uint16_t *dh, *dl; int K, N, roff;
    if (m == 0)      { src = W1l; dh = g_w1h; dl = g_w1lo; K = D_IN;  N = H1DIM; roff = 0; }
    else if (m == 1) { src = W1r; dh = g_w1h; dl = g_w1lo; K = D_IN;  N = H1DIM; roff = H1DIM; }
    else if (m == 2) { src = W2l; dh = g_w2h; dl = g_w2lo; K = H1DIM; N = HID; roff = 0; }
    else             { src = W2r; dh = g_w2h; dl = g_w2lo; K = H1DIM; N = HID; roff = HID; }
    int total = K * N;
    for (int t = blockIdx.x * blockDim.x + threadIdx.x; t < total; t += gridDim.x * blockDim.x) {
        int k = t / N, n = t % N;
        uint16_t hi, lo;
        split_bf16(src[t], hi, lo);
        dh[(size_t)(roff + n) * K + k] = hi;
        dl[(size_t)(roff + n) * K + k] = lo;
    }
}

// ---------------- bf16x3 tensor-core GEMM, cp.async double-buffered ----------------
// C[M,Ntot] = A[M,K] @ W[K,Ntot] via Ah*Bh + Ah*Bl + Al*Bh.
// asel: 0 = x split, 1 = h1 split.  lay: 0 = (w1, g_t1), 1 = (w2, g_t2).
template <int BM, int BN, int BK, int WM, int WN>
__global__ void __launch_bounds__((BM / WM) * (BN / WN) * 32)
mma_gemm_db_kernel(int M, int Ntot, int K, int asel, int lay) {
    constexpr int WARPS_M = BM / WM;
    constexpr int WARPS_N = BN / WN;
    constexpr int THREADS = WARPS_M * WARPS_N * 32;
    constexpr int MT = WM / 16;
    constexpr int NT = WN / 8;
    constexpr int AST = BK + 8;           // conflict-free fragment stride
    constexpr int A_SZ = BM * AST;        // u16 per (hi or lo)
    constexpr int B_SZ = BN * AST;
    constexpr int STAGE = 2 * A_SZ + 2 * B_SZ;

    extern __shared__ uint16_t sm[];

    const uint16_t* Ah = asel == 0 ? g_xh  : g_h1h;
    const uint16_t* Al = asel == 0 ? g_xlo : g_h1l;
    const uint16_t* Bh = lay == 0 ? g_w1h  : g_w2h;
    const uint16_t* Bl = lay == 0 ? g_w1lo : g_w2lo;
    float* C = lay == 0 ? g_t1 : g_t2;

    int tid = threadIdx.x;
    int wid = tid >> 5, lane = tid & 31;
    int gid = lane >> 2, tig = lane & 3;
    int wm = wid / WARPS_N, wn = wid % WARPS_N;
    int row0 = blockIdx.y * BM;
    int n0 = blockIdx.x * BN;

    float acc[MT][NT][4];
    #pragma unroll
    for (int i = 0; i < MT; i++)
        #pragma unroll
        for (int j = 0; j < NT; j++)
            #pragma unroll
            for (int q = 0; q < 4; q++) acc[i][j][q] = 0.f;

    const int T = K / BK;

    auto load_stage = [&](int s, int k0) {
        uint16_t* base = sm + s * STAGE;
        #pragma unroll
        for (int idx = tid; idx < BM * (BK / 8); idx += THREADS) {
            int r = idx / (BK / 8);
            int c = (idx % (BK / 8)) * 8;
            int gr = row0 + r;
            bool v = gr < M;
            size_t off = (size_t)(v ? gr : 0) * K + k0 + c;
            cpa16_cg(base + r * AST + c, Ah + off, v);
            cpa16_cg(base + A_SZ + r * AST + c, Al + off, v);
        }
        #pragma unroll
        for (int idx = tid; idx < BN * (BK / 8); idx += THREADS) {
            int r = idx / (BK / 8);
            int c = (idx % (BK / 8)) * 8;
            size_t off = (size_t)(n0 + r) * K + k0 + c;
            cpa16_ca(base + 2 * A_SZ + r * AST + c, Bh + off);
            cpa16_ca(base + 2 * A_SZ + B_SZ + r * AST + c, Bl + off);
        }
        CP_COMMIT();
    };

    load_stage(0, 0);
    for (int i = 0; i < T; i++) {
        if (i + 1 < T) {
            load_stage((i + 1) & 1, (i + 1) * BK);
            CP_WAIT(1);
        } else {
            CP_WAIT(0);
        }
        __syncthreads();

        const uint16_t* sAh = sm + (i & 1) * STAGE;
        const uint16_t* sAl = sAh + A_SZ;
        const uint16_t* sBh = sAh + 2 * A_SZ;
        const uint16_t* sBl = sBh + B_SZ;

        #pragma unroll
        for (int kk = 0; kk < BK; kk += 16) {
            uint32_t ah[MT][4], al[MT][4];
            #pragma unroll
            for (int mt = 0; mt < MT; mt++) {
                int r = wm * WM + mt * 16 + gid;
                ah[mt][0] = *(const uint32_t*)&sAh[r * AST + kk + 2 * tig];
                ah[mt][1] = *(const uint32_t*)&sAh[(r + 8) * AST + kk + 2 * tig];
                ah[mt][2] = *(const uint32_t*)&sAh[r * AST + kk + 8 + 2 * tig];
                ah[mt][3] = *(const uint32_t*)&sAh[(r + 8) * AST + kk + 8 + 2 * tig];
                al[mt][0] = *(const uint32_t*)&sAl[r * AST + kk + 2 * tig];
                al[mt][1] = *(const uint32_t*)&sAl[(r + 8) * AST + kk + 2 * tig];
                al[mt][2] = *(const uint32_t*)&sAl[r * AST + kk + 8 + 2 * tig];
                al[mt][3] = *(const uint32_t*)&sAl[(r + 8) * AST + kk + 8 + 2 * tig];
            }
            #pragma unroll
            for (int nt = 0; nt < NT; nt++) {
                int bn = wn * WN + nt * 8 + gid;
                uint32_t bh0 = *(const uint32_t*)&sBh[bn * AST + kk + 2 * tig];
                uint32_t bh1 = *(const uint32_t*)&sBh[bn * AST + kk + 8 + 2 * tig];
                uint32_t bl0 = *(const uint32_t*)&sBl[bn * AST + kk + 2 * tig];
                uint32_t bl1 = *(const uint32_t*)&sBl[bn * AST + kk + 8 + 2 * tig];
                #pragma unroll
                for (int mt = 0; mt < MT; mt++) {
                    mma16816(acc[mt][nt], ah[mt], bh0, bh1);
                    mma16816(acc[mt][nt], ah[mt], bl0, bl1);
                    mma16816(acc[mt][nt], al[mt], bh0, bh1);
                }
            }
        }
        __syncthreads();
    }

    #pragma unroll
    for (int mt = 0; mt < MT; mt++) {
        #pragma unroll
        for (int nt = 0; nt < NT; nt++) {
            int gr = row0 + wm * WM + mt * 16 + gid;
            int gc = n0 + wn * WN + nt * 8 + 2 * tig;
            if (gr < M)
                *(float2*)&C[(size_t)gr * Ntot + gc] = make_float2(acc[mt][nt][0], acc[mt][nt][1]);
            if (gr + 8 < M)
                *(float2*)&C[(size_t)(gr + 8) * Ntot + gc] = make_float2(acc[mt][nt][2], acc[mt][nt][3]);
        }
    }
}

// ---------------- GAT layer 1: warp per dst node, online softmax (1 exp/edge) ----------------
__global__ void gat1_kernel(const float* __restrict__ att, const float* __restrict__ bias,
                            int n) {
    int warp = (blockIdx.x * blockDim.x + threadIdx.x) >> 5;
    int lane = threadIdx.x & 31;
    if (warp >= n) return;
    int head = lane >> 2, sub = lane & 3;

    const float4* xr4 = (const float4*)(g_t1 + (size_t)warp * T1W + H1DIM + lane * 8);
    float4 r0 = xr4[0], r1 = xr4[1];
    float xrv[8] = {r0.x, r0.y, r0.z, r0.w, r1.x, r1.y, r1.z, r1.w};
    float av[8];
    #pragma unroll
    for (int k = 0; k < 8; k++) av[k] = att[head * HID + sub * 8 + k];

    float acc[8] = {0.f, 0.f, 0.f, 0.f, 0.f, 0.f, 0.f, 0.f};
    float m = -1e30f, denom = 0.f;

    int s = g_rowstart[warp], e = g_rowstart[warp + 1];
    int src_next = (s < e) ? g_col[s] : 0;
    for (int j = s; j < e; j++) {
        int src = src_next;
        if (j + 1 < e) src_next = g_col[j + 1];   // prefetch index off the critical path
        const float4* p4 = (const float4*)(g_t1 + (size_t)src * T1W + lane * 8);
        float4 a = p4[0], b = p4[1];
        float xv[8] = {a.x, a.y, a.z, a.w, b.x, b.y, b.z, b.w};
        float logit = 0.f;
        #pragma unroll
        for (int k = 0; k < 8; k++) {
            float t = xv[k] + xrv[k];
            t = t > 0.f ? t : NEG_SLOPE * t;
            logit += t * av[k];
        }
        logit += __shfl_xor_sync(0xFFFFFFFFu, logit, 1);
        logit += __shfl_xor_sync(0xFFFFFFFFu, logit, 2);
        // one exp: exactly one of (sc, w) is exp(-|logit-m|), the other 1
        float ex = __expf(-fabsf(logit - m));
        bool keep = logit <= m;
        float sc = keep ? 1.f : ex;
        float w  = keep ? ex : 1.f;
        m = fmaxf(m, logit);
        denom = denom * sc + w;
        #pragma unroll
        for (int k = 0; k < 8; k++) acc[k] = acc[k] * sc + w * xv[k];
    }
    float inv = 1.f / fmaxf(denom, 1e-16f);
    uint16_t hv[8], lv[8];
    #pragma unroll
    for (int k = 0; k < 8; k++) {
        float v = acc[k] * inv + bias[lane * 8 + k];
        v = v > 0.f ? v : expm1f(v);      // ELU
        split_bf16(v, hv[k], lv[k]);
    }
    *(uint4*)&g_h1h[(size_t)warp * H1DIM + lane * 8] = *(const uint4*)hv;
    *(uint4*)&g_h1l[(size_t)warp * H1DIM + lane * 8] = *(const uint4*)lv;
}

// ---------------- GAT layer 2 (1 head) + fused final linear ----------------
__global__ void gat2_kernel(const float* __restrict__ att, const float* __restrict__ bias,
                            const float* __restrict__ Wlin, const float* __restrict__ blin,
                            float* __restrict__ out, int n) {
    __shared__ float sh[8][HID];
    int warp = (blockIdx.x * blockDim.x + threadIdx.x) >> 5;
    int lane = threadIdx.x & 31;
    int wl = threadIdx.x >> 5;
    if (warp >= n) return;

    float xrv = g_t2[(size_t)warp * T2W + HID + lane];
    float av  = att[lane];
    float acc = 0.f, m = -1e30f, denom = 0.f;

    int s = g_rowstart[warp], e = g_rowstart[warp + 1];
    int src_next = (s < e) ? g_col[s] : 0;
    for (int j = s; j < e; j++) {
        int src = src_next;
        if (j + 1 < e) src_next = g_col[j + 1];
        float xv = g_t2[(size_t)src * T2W + lane];
        float t = xv + xrv;
        t = t > 0.f ? t : NEG_SLOPE * t;
        float logit = t * av;
        #pragma unroll
        for (int d = 16; d >= 1; d >>= 1) logit += __shfl_xor_sync(0xFFFFFFFFu, logit, d);
        float ex = __expf(-fabsf(logit - m));
        bool keep = logit <= m;
        float sc = keep ? 1.f : ex;
        float w  = keep ? ex : 1.f;
        m = fmaxf(m, logit);
        denom = denom * sc + w;
        acc = acc * sc + w * xv;
    }
    float h2 = acc / fmaxf(denom, 1e-16f) + bias[lane];
    h2 = h2 > 0.f ? h2 : expm1f(h2);          // ELU

    sh[wl][lane] = h2;
    __syncwarp();
    if (lane < OUTD) {
        float sum = blin[lane];
        #pragma unroll
        for (int c = 0; c < HID; c++) sum += sh[wl][c] * Wlin[c * OUTD + lane];
        out[(size_t)warp * OUTD + lane] = sum;
    }
}

// ---------------- launch ----------------
extern "C" void kernel_launch(void* const* d_in, const int* in_sizes, int n_in,
                              void* d_out, int out_size) {
    const float* x    = (const float*)d_in[0];
    const int*   ei   = (const int*)d_in[1];     // int32 (JAX x64 disabled)
    const float* W1l  = (const float*)d_in[2];
    const float* W1r  = (const float*)d_in[3];
    const float* att1 = (const float*)d_in[4];
    const float* b1   = (const float*)d_in[5];
    const float* W2l  = (const float*)d_in[6];
    const float* W2r  = (const float*)d_in[7];
    const float* att2 = (const float*)d_in[8];
    const float* b2   = (const float*)d_in[9];
    const float* Wlin = (const float*)d_in[10];
    const float* blin = (const float*)d_in[11];
    float* out = (float*)d_out;

    int N = in_sizes[0] / D_IN;
    int E = in_sizes[1] / 2;

    // side stream + events: created once on the first (uncaptured) correctness
    // call; re-used by every later call. Fork/join via events is graph-capture
    // legal and produces two parallel branches in the captured graph.
    static cudaStream_t s_csr = nullptr;
    static cudaEvent_t ev_fork = nullptr, ev_join = nullptr;
    if (s_csr == nullptr) {
        cudaStreamCreateWithFlags(&s_csr, cudaStreamNonBlocking);
        cudaEventCreateWithFlags(&ev_fork, cudaEventDisableTiming);
        cudaEventCreateWithFlags(&ev_join, cudaEventDisableTiming);
    }

    // dynamic smem opt-in (idempotent attribute set — capture-safe)
    cudaFuncSetAttribute(mma_gemm_db_kernel<128, 128, 32, 32, 64>,
                         cudaFuncAttributeMaxDynamicSharedMemorySize, 81920);
    cudaFuncSetAttribute(mma_gemm_db_kernel<128, 64, 32, 32, 32>,
                         cudaFuncAttributeMaxDynamicSharedMemorySize, 61440);

    // ---- fork: CSR build on side stream, transforms on main stream ----
    cudaEventRecord(ev_fork, 0);
    cudaStreamWaitEvent(s_csr, ev_fork, 0);

    // CSR branch (side stream)
    zero_counts_kernel<<<(N + 255) / 256, 256, 0, s_csr>>>(N);
    hist_kernel<<<(E + 255) / 256, 256, 0, s_csr>>>(ei, E, N);
    scan_kernel<<<1, 1024, 0, s_csr>>>(N);
    scatter_kernel<<<(E + N + 255) / 256, 256, 0, s_csr>>>(ei, E, N);
    cudaEventRecord(ev_join, s_csr);

    // main branch: splits + layer-1 GEMM
    split_x_kernel<<<(N * D_IN + 255) / 256, 256>>>(x, N * D_IN);
    {
        dim3 g(64, 4);
        split_w_kernel<<<g, 256>>>(W1l, W1r, W2l, W2r);
    }
    {
        dim3 grid(T1W / 128, (N + 127) / 128);
        mma_gemm_db_kernel<128, 128, 32, 32, 64><<<grid, 256, 81920>>>(N, T1W, D_IN, 0, 0);
    }

    // ---- join: gat1 needs both CSR and t1 ----
    cudaStreamWaitEvent(0, ev_join, 0);

    gat1_kernel<<<(N * 32 + 255) / 256, 256>>>(att1, b1, N);

    // layer-2 transform (fused): t2 = h1 @ [W2l|W2r]
    {
        dim3 grid(T2W / 64, (N + 127) / 128);
        mma_gemm_db_kernel<128, 64, 32, 32, 32><<<grid, 256, 61440>>>(N, T2W, H1DIM, 1, 1);
    }

    // GAT layer 2 + final linear
    gat2_kernel<<<(N * 32 + 255) / 256, 256>>>(att2, b2, Wlin, blin, out, N);
}